// round 4
// baseline (speedup 1.0000x reference)
#include <cuda_runtime.h>
#include <cstdint>

#define HEADS 4
#define CB    8192
#define D     64
#define M     8192            // B*N = 4*2048
#define DIM   256             // HEADS*D
#define QSIZE (M*DIM)         // 2,097,152 floats of quantize output
#define TM 64
#define TN 64

// scratch for per-code squared norms (no cudaMalloc allowed)
__device__ float g_y2[HEADS*CB];

// ---------------------------------------------------------------------------
// y2[h*CB+c] = sum_k embed[h][c][k]^2   (one warp per code)
// ---------------------------------------------------------------------------
__global__ void vq_y2_kernel(const float* __restrict__ embed) {
    int gw   = (blockIdx.x * blockDim.x + threadIdx.x) >> 5;
    int lane = threadIdx.x & 31;
    if (gw >= HEADS * CB) return;
    float2 v = reinterpret_cast<const float2*>(embed + (size_t)gw * D)[lane];
    float s = fmaf(v.x, v.x, v.y * v.y);
    #pragma unroll
    for (int o = 16; o; o >>= 1) s += __shfl_xor_sync(0xffffffffu, s, o);
    if (lane == 0) g_y2[gw] = s;
}

// packed f32x2 FMA — ptxas never emits this from C++; it's the full-rate fp32 path
__device__ __forceinline__ void ffma2(unsigned long long& acc,
                                      unsigned long long a,
                                      unsigned long long b) {
    asm("fma.rn.f32x2 %0, %1, %2, %0;" : "+l"(acc) : "l"(a), "l"(b));
}

// ---------------------------------------------------------------------------
// Fused distance-GEMM + argmax + gather.
// grid = (M/TM, HEADS), block = 256. Each block: 64 queries vs all 8192 codes.
// score(c) = x.e_c - 0.5*|e_c|^2  (monotone-equivalent to -sqrt distance)
// ---------------------------------------------------------------------------
__global__ __launch_bounds__(256, 2)
void vq_main_kernel(const float* __restrict__ x, const float* __restrict__ embed,
                    float* __restrict__ out, int out_size) {
    __shared__ float4 Xs[TM * 16];   // [r][kq] linear, 16 float4 per row
    __shared__ float4 Es[TN * 16];   // [c][kq ^ ((c>>2)&15)] swizzled
    __shared__ float  y2s[TN];
    __shared__ int    inds[TM];

    const int h  = blockIdx.y;
    const int m0 = blockIdx.x * TM;
    const int t  = threadIdx.x;
    const int tx = t & 15;           // code-frag coordinate (16)
    const int ty = t >> 4;           // query-frag coordinate (16)

    // ---- load X tile once: Xs[r*16+kq] = x[m0+r][h*64 + 4kq .. +3] ----
    #pragma unroll
    for (int s = 0; s < 4; s++) {
        int slot = t + s * 256;
        int r = slot >> 4, kq = slot & 15;
        Xs[slot] = *reinterpret_cast<const float4*>(
            x + (size_t)(m0 + r) * DIM + h * D + kq * 4);
    }

    float rmax[4];
    int   ridx[4];
    #pragma unroll
    for (int i = 0; i < 4; i++) { rmax[i] = -3.4e38f; ridx[i] = 0; }

    const float* ebase  = embed + (size_t)h * CB * D;
    const float* y2base = g_y2 + h * CB;

    for (int tile = 0; tile < CB / TN; tile++) {
        const int n0 = tile * TN;
        __syncthreads();             // previous iteration done reading Es/y2s
        // ---- load E tile (swizzled so frag reads are conflict-free) ----
        #pragma unroll
        for (int s = 0; s < 4; s++) {
            int slot = t + s * 256;
            int c = slot >> 4, kq = slot & 15;
            float4 v = *reinterpret_cast<const float4*>(
                ebase + (size_t)(n0 + c) * D + kq * 4);
            Es[c * 16 + (kq ^ ((c >> 2) & 15))] = v;
        }
        if (t < TN) y2s[t] = y2base[n0 + t];
        __syncthreads();

        // ---- 4x4 frag accumulation over K=64 in packed f32x2 ----
        unsigned long long acc[4][4];
        #pragma unroll
        for (int i = 0; i < 4; i++)
            #pragma unroll
            for (int j = 0; j < 4; j++) acc[i][j] = 0ull;   // (0.f, 0.f)

        const ulonglong2* XsU = reinterpret_cast<const ulonglong2*>(Xs);
        const ulonglong2* EsU = reinterpret_cast<const ulonglong2*>(Es);
        #pragma unroll
        for (int kq = 0; kq < 16; kq++) {
            const int ep = kq ^ tx;          // Es physical float4 index (swizzle)
            ulonglong2 ev[4], xv[4];
            #pragma unroll
            for (int j = 0; j < 4; j++) ev[j] = EsU[(4 * tx + j) * 16 + ep];
            #pragma unroll
            for (int i = 0; i < 4; i++) xv[i] = XsU[(4 * ty + i) * 16 + kq];
            #pragma unroll
            for (int i = 0; i < 4; i++)
                #pragma unroll
                for (int j = 0; j < 4; j++) {
                    ffma2(acc[i][j], xv[i].x, ev[j].x);   // k even pair
                    ffma2(acc[i][j], xv[i].y, ev[j].y);   // k odd pair
                }
        }

        // ---- epilogue: running argmax (first-index tie-break via strict >) ----
        #pragma unroll
        for (int j = 0; j < 4; j++) {
            const float yh = 0.5f * y2s[4 * tx + j];
            const int   cg = n0 + 4 * tx + j;
            #pragma unroll
            for (int i = 0; i < 4; i++) {
                unsigned long long a = acc[i][j];
                float lo = __uint_as_float((unsigned)a);
                float hi = __uint_as_float((unsigned)(a >> 32));
                float sc = lo + hi - yh;
                if (sc > rmax[i]) { rmax[i] = sc; ridx[i] = cg; }
            }
        }
    }

    // ---- reduce (max, idx) across the 16 tx lanes; ties -> smaller idx ----
    #pragma unroll
    for (int i = 0; i < 4; i++) {
        float v = rmax[i];
        int  id = ridx[i];
        #pragma unroll
        for (int o = 8; o; o >>= 1) {
            float ov = __shfl_xor_sync(0xffffffffu, v, o);
            int   oi = __shfl_xor_sync(0xffffffffu, id, o);
            if (ov > v || (ov == v && oi < id)) { v = ov; id = oi; }
        }
        if (tx == 0) inds[4 * ty + i] = id;
    }
    __syncthreads();

    // ---- write indices (as float, layout b n h) ----
    if (out_size >= QSIZE + M * HEADS && t < TM) {
        out[QSIZE + (size_t)(m0 + t) * HEADS + h] = (float)inds[t];
    }
    // ---- gather quantized codes (layout b n (h d)) ----
    #pragma unroll
    for (int s = 0; s < 4; s++) {
        int slot = t + s * 256;
        int r = slot >> 4, kq = slot & 15;
        int id = inds[r];
        float4 v = *reinterpret_cast<const float4*>(ebase + (size_t)id * D + kq * 4);
        *reinterpret_cast<float4*>(out + (size_t)(m0 + r) * DIM + h * D + kq * 4) = v;
    }
}

extern "C" void kernel_launch(void* const* d_in, const int* in_sizes, int n_in,
                              void* d_out, int out_size) {
    const float* x     = (const float*)d_in[0];   // [4,2048,256]
    const float* embed = (const float*)d_in[1];   // [4,8192,64]
    float* out = (float*)d_out;

    // 1) per-code squared norms (32768 warps)
    vq_y2_kernel<<<(HEADS * CB) / 8, 256>>>(embed);

    // 2) fused distance GEMM + argmax + gather
    dim3 grid(M / TM, HEADS);
    vq_main_kernel<<<grid, 256>>>(x, embed, out, out_size);
}